// round 8
// baseline (speedup 1.0000x reference)
#include <cuda_runtime.h>
#include <cuda_bf16.h>

#define VEC8_ROW 2048              // 8-float groups per T-row (T=16384)
#define BLK      256
#define GRID_S   1024              // specialized grid: 2^18 threads, 4 vec8 each
#define STRIDE_S (GRID_S * BLK)    // 262144
#define NBLOCKS_G 1184             // generic fallback grid

#define NUM_SCALE 65536.0          // 2^16
#define DEN_SCALE 1073741824.0     // 2^30

__device__ long long g_num_acc = 0;
__device__ long long g_den_acc = 0;
__device__ unsigned int g_ticket = 0;

struct f8 { float v[8]; };

__device__ __forceinline__ float warp_sum(float x) {
#pragma unroll
    for (int o = 16; o; o >>= 1) x += __shfl_xor_sync(0xffffffffu, x, o);
    return x;
}

// log(sigmoid(x)) = -log(1 + exp(-x)); EPS negligible at 1e-3 tolerance
__device__ __forceinline__ float log_sig(float x) {
    return -__logf(1.0f + __expf(-x));
}

__device__ __forceinline__ f8 ldg8(const float* p) {
    f8 r;
    asm("ld.global.nc.L2::evict_last.v8.b32 {%0,%1,%2,%3,%4,%5,%6,%7}, [%8];"
        : "=f"(r.v[0]), "=f"(r.v[1]), "=f"(r.v[2]), "=f"(r.v[3]),
          "=f"(r.v[4]), "=f"(r.v[5]), "=f"(r.v[6]), "=f"(r.v[7])
        : "l"(p));
    return r;
}

// shared epilogue: block-reduce -> deterministic fixed-point global acc -> last-block finish
__device__ __forceinline__ void finish(float num, float den, float* out, int nblocks) {
    num = warp_sum(num);
    den = warp_sum(den);

    __shared__ float sn[BLK / 32], sd[BLK / 32];
    __shared__ unsigned int s_ticket;
    int wid = threadIdx.x >> 5, lid = threadIdx.x & 31;
    if (lid == 0) { sn[wid] = num; sd[wid] = den; }
    __syncthreads();
    if (threadIdx.x == 0) {
        float bn = 0.0f, bd = 0.0f;
#pragma unroll
        for (int i = 0; i < BLK / 32; ++i) { bn += sn[i]; bd += sd[i]; }
        long long qn = __double2ll_rn((double)bn * NUM_SCALE);
        long long qd = __double2ll_rn((double)bd * DEN_SCALE);
        atomicAdd((unsigned long long*)&g_num_acc, (unsigned long long)qn);
        atomicAdd((unsigned long long*)&g_den_acc, (unsigned long long)qd);
        __threadfence();
        s_ticket = atomicAdd(&g_ticket, 1u);
    }
    __syncthreads();

    if (s_ticket == (unsigned)(nblocks - 1) && threadIdx.x == 0) {
        long long qn = atomicAdd((unsigned long long*)&g_num_acc, 0ull);
        long long qd = atomicAdd((unsigned long long*)&g_den_acc, 0ull);
        out[0] = (float)(((double)qn / NUM_SCALE) / ((double)qd / DEN_SCALE));
        g_num_acc = 0;
        g_den_acc = 0;
        g_ticket = 0;
        __threadfence();
    }
}

// specialized: nvec8 == 2^20, perfectly balanced, compile-time trip count
__global__ void __launch_bounds__(BLK, 7)
reinforce_s(const float* __restrict__ lp,
            const float* __restrict__ lg,
            const float* __restrict__ wt,
            float* __restrict__ out)
{
    const int tid = blockIdx.x * BLK + threadIdx.x;
    float num = 0.0f, den = 0.0f;

#pragma unroll
    for (int k = 0; k < 4; ++k) {
        const int v = tid + k * STRIDE_S;
        const int off = v << 3;
        f8 a = ldg8(lp + off);
        f8 b = ldg8(lg + off);
        f8 c = ldg8(wt + off);
        float tb = (float)(((v & (VEC8_ROW - 1)) << 3) + 1);
#pragma unroll
        for (int j = 0; j < 8; ++j) {
            num = fmaf(c.v[j] * c.v[j] * log_sig(b.v[j]) * a.v[j],
                       tb + (float)j, num);
            den += c.v[j];
        }
    }
    finish(num, den, out, GRID_S);
}

// generic fallback for any n divisible by 8
__global__ void __launch_bounds__(BLK)
reinforce_g(const float* __restrict__ lp,
            const float* __restrict__ lg,
            const float* __restrict__ wt,
            float* __restrict__ out,
            int nvec8)
{
    float num = 0.0f, den = 0.0f;
    const int stride = gridDim.x * blockDim.x;
    for (int v = blockIdx.x * blockDim.x + threadIdx.x; v < nvec8; v += stride) {
        const int off = v << 3;
        f8 a = ldg8(lp + off);
        f8 b = ldg8(lg + off);
        f8 c = ldg8(wt + off);
        float tb = (float)(((v & (VEC8_ROW - 1)) << 3) + 1);
#pragma unroll
        for (int j = 0; j < 8; ++j) {
            num = fmaf(c.v[j] * c.v[j] * log_sig(b.v[j]) * a.v[j],
                       tb + (float)j, num);
            den += c.v[j];
        }
    }
    finish(num, den, out, gridDim.x);
}

extern "C" void kernel_launch(void* const* d_in, const int* in_sizes, int n_in,
                              void* d_out, int out_size)
{
    const float* lp = (const float*)d_in[0];  // log_probs [B,T]
    const float* lg = (const float*)d_in[1];  // logits    [B,T,1]
    const float* wt = (const float*)d_in[2];  // weight    [B,T]
    float* out = (float*)d_out;

    int n = in_sizes[0];     // 8388608
    int nvec8 = n >> 3;      // 1048576 = 2^20

    if (nvec8 == (1 << 20)) {
        reinforce_s<<<GRID_S, BLK>>>(lp, lg, wt, out);
    } else {
        reinforce_g<<<NBLOCKS_G, BLK>>>(lp, lg, wt, out, nvec8);
    }
}

// round 9
// speedup vs baseline: 1.4989x; 1.4989x over previous
#include <cuda_runtime.h>
#include <cuda_bf16.h>

#define VEC8_ROW 2048          // 8-float groups per T-row (T=16384)
#define BLK      256
#define NBLOCKS  1184          // 148 SMs * 8 CTAs, exactly one full wave

#define NUM_SCALE 65536.0           // 2^16
#define DEN_SCALE 1073741824.0      // 2^30

__device__ long long g_num_acc = 0;
__device__ long long g_den_acc = 0;
__device__ unsigned int g_ticket = 0;

struct f8 { float v[8]; };

__device__ __forceinline__ float warp_sum(float x) {
#pragma unroll
    for (int o = 16; o; o >>= 1) x += __shfl_xor_sync(0xffffffffu, x, o);
    return x;
}

// log(sigmoid(x)) = -log(1 + exp(-x)); EPS term negligible at 1e-3 tolerance
__device__ __forceinline__ float log_sig(float x) {
    return -__logf(1.0f + __expf(-x));
}

__device__ __forceinline__ f8 ldg8(const float* p) {
    f8 r;
    asm("ld.global.nc.L2::evict_last.v8.b32 {%0,%1,%2,%3,%4,%5,%6,%7}, [%8];"
        : "=f"(r.v[0]), "=f"(r.v[1]), "=f"(r.v[2]), "=f"(r.v[3]),
          "=f"(r.v[4]), "=f"(r.v[5]), "=f"(r.v[6]), "=f"(r.v[7])
        : "l"(p));
    return r;
}

__global__ void __launch_bounds__(BLK)
reinforce_fused(const float* __restrict__ lp,
                const float* __restrict__ lg,
                const float* __restrict__ wt,
                float* __restrict__ out,
                int nvec8)
{
    // dual accumulators: halve the serial FFMA/FADD chain depth
    float num0 = 0.0f, num1 = 0.0f, den0 = 0.0f, den1 = 0.0f;
    const int stride = gridDim.x * blockDim.x;
    for (int v = blockIdx.x * blockDim.x + threadIdx.x; v < nvec8; v += stride) {
        const int off = v << 3;
        f8 a = ldg8(lp + off);
        f8 b = ldg8(lg + off);
        f8 c = ldg8(wt + off);
        float tb = (float)(((v & (VEC8_ROW - 1)) << 3) + 1);

#pragma unroll
        for (int j = 0; j < 8; j += 2) {
            num0 = fmaf(c.v[j]     * c.v[j]     * log_sig(b.v[j])     * a.v[j],
                        tb + (float)j,        num0);
            num1 = fmaf(c.v[j + 1] * c.v[j + 1] * log_sig(b.v[j + 1]) * a.v[j + 1],
                        tb + (float)(j + 1),  num1);
            den0 += c.v[j];
            den1 += c.v[j + 1];
        }
    }
    float num = num0 + num1;
    float den = den0 + den1;

    // block reduction
    num = warp_sum(num);
    den = warp_sum(den);

    __shared__ float sn[BLK / 32], sd[BLK / 32];
    __shared__ unsigned int s_ticket;
    int wid = threadIdx.x >> 5, lid = threadIdx.x & 31;
    if (lid == 0) { sn[wid] = num; sd[wid] = den; }
    __syncthreads();
    if (threadIdx.x == 0) {
        float bn = 0.0f, bd = 0.0f;
#pragma unroll
        for (int i = 0; i < BLK / 32; ++i) { bn += sn[i]; bd += sd[i]; }
        // Deterministic order-independent accumulation: 64-bit fixed point.
        long long qn = __double2ll_rn((double)bn * NUM_SCALE);
        long long qd = __double2ll_rn((double)bd * DEN_SCALE);
        atomicAdd((unsigned long long*)&g_num_acc, (unsigned long long)qn);
        atomicAdd((unsigned long long*)&g_den_acc, (unsigned long long)qd);
        __threadfence();
        s_ticket = atomicAdd(&g_ticket, 1u);
    }
    __syncthreads();

    // last block: trivial finish
    if (s_ticket == (unsigned)(gridDim.x - 1) && threadIdx.x == 0) {
        long long qn = atomicAdd((unsigned long long*)&g_num_acc, 0ull);
        long long qd = atomicAdd((unsigned long long*)&g_den_acc, 0ull);
        out[0] = (float)(((double)qn / NUM_SCALE) / ((double)qd / DEN_SCALE));
        g_num_acc = 0;
        g_den_acc = 0;
        g_ticket = 0;
        __threadfence();
    }
}

extern "C" void kernel_launch(void* const* d_in, const int* in_sizes, int n_in,
                              void* d_out, int out_size)
{
    const float* lp = (const float*)d_in[0];  // log_probs [B,T]
    const float* lg = (const float*)d_in[1];  // logits    [B,T,1]
    const float* wt = (const float*)d_in[2];  // weight    [B,T]
    float* out = (float*)d_out;

    int n = in_sizes[0];     // 8388608
    int nvec8 = n >> 3;      // 1048576

    reinforce_fused<<<NBLOCKS, BLK>>>(lp, lg, wt, out, nvec8);
}

// round 10
// speedup vs baseline: 1.5619x; 1.0420x over previous
#include <cuda_runtime.h>
#include <cuda_bf16.h>

#define VEC8_ROW 2048          // 8-float groups per T-row (T=16384)
#define BLK      256
#define NBLOCKS  1184          // 148 SMs * 8 CTAs, exactly one full wave

#define NUM_SCALE 65536.0           // 2^16
#define DEN_SCALE 1073741824.0      // 2^30

__device__ long long g_num_acc = 0;
__device__ long long g_den_acc = 0;
__device__ unsigned int g_ticket = 0;

struct f8 { float v[8]; };

__device__ __forceinline__ float warp_sum(float x) {
#pragma unroll
    for (int o = 16; o; o >>= 1) x += __shfl_xor_sync(0xffffffffu, x, o);
    return x;
}

// log(sigmoid(x)) = -log(1 + exp(-x)); EPS term negligible at 1e-3 tolerance
__device__ __forceinline__ float log_sig(float x) {
    return -__logf(1.0f + __expf(-x));
}

__device__ __forceinline__ f8 ldg8(const float* p) {
    f8 r;
    asm("ld.global.nc.L2::evict_last.v8.b32 {%0,%1,%2,%3,%4,%5,%6,%7}, [%8];"
        : "=f"(r.v[0]), "=f"(r.v[1]), "=f"(r.v[2]), "=f"(r.v[3]),
          "=f"(r.v[4]), "=f"(r.v[5]), "=f"(r.v[6]), "=f"(r.v[7])
        : "l"(p));
    return r;
}

__global__ void __launch_bounds__(BLK)
reinforce_fused(const float* __restrict__ lp,
                const float* __restrict__ lg,
                const float* __restrict__ wt,
                float* __restrict__ out,
                int nvec8)
{
    float num = 0.0f, den = 0.0f;
    const int stride = gridDim.x * blockDim.x;
    for (int v = blockIdx.x * blockDim.x + threadIdx.x; v < nvec8; v += stride) {
        const int off = v << 3;
        f8 b = ldg8(lg + off);   // longest consumer chain (MUFU) -> issue first
        f8 a = ldg8(lp + off);
        f8 c = ldg8(wt + off);
        float tb = (float)(((v & (VEC8_ROW - 1)) << 3) + 1);

#pragma unroll
        for (int k = 0; k < 8; ++k) {
            num = fmaf(c.v[k] * c.v[k] * log_sig(b.v[k]) * a.v[k],
                       tb + (float)k, num);
            den += c.v[k];
        }
    }

    // block reduction
    num = warp_sum(num);
    den = warp_sum(den);

    __shared__ float sn[BLK / 32], sd[BLK / 32];
    __shared__ unsigned int s_ticket;
    int wid = threadIdx.x >> 5, lid = threadIdx.x & 31;
    if (lid == 0) { sn[wid] = num; sd[wid] = den; }
    __syncthreads();
    if (threadIdx.x == 0) {
        float bn = 0.0f, bd = 0.0f;
#pragma unroll
        for (int i = 0; i < BLK / 32; ++i) { bn += sn[i]; bd += sd[i]; }
        // Deterministic order-independent accumulation: 64-bit fixed point.
        // |num| ~ 5e7 -> q <= 1.4e14 << 2^62; rounding 2^-17 * 1184 ~ 1e-2 abs.
        long long qn = __double2ll_rn((double)bn * NUM_SCALE);
        long long qd = __double2ll_rn((double)bd * DEN_SCALE);
        atomicAdd((unsigned long long*)&g_num_acc, (unsigned long long)qn);
        atomicAdd((unsigned long long*)&g_den_acc, (unsigned long long)qd);
        __threadfence();
        s_ticket = atomicAdd(&g_ticket, 1u);
    }
    __syncthreads();

    // last block: trivial finish (2 loads, 1 divide, 1 store, reset)
    if (s_ticket == (unsigned)(gridDim.x - 1) && threadIdx.x == 0) {
        long long qn = atomicAdd((unsigned long long*)&g_num_acc, 0ull);
        long long qd = atomicAdd((unsigned long long*)&g_den_acc, 0ull);
        out[0] = (float)(((double)qn / NUM_SCALE) / ((double)qd / DEN_SCALE));
        g_num_acc = 0;
        g_den_acc = 0;
        g_ticket = 0;
        __threadfence();
    }
}

extern "C" void kernel_launch(void* const* d_in, const int* in_sizes, int n_in,
                              void* d_out, int out_size)
{
    const float* lp = (const float*)d_in[0];  // log_probs [B,T]
    const float* lg = (const float*)d_in[1];  // logits    [B,T,1]
    const float* wt = (const float*)d_in[2];  // weight    [B,T]
    float* out = (float*)d_out;

    int n = in_sizes[0];     // 8388608
    int nvec8 = n >> 3;      // 1048576

    reinforce_fused<<<NBLOCKS, BLK>>>(lp, lg, wt, out, nvec8);
}